// round 10
// baseline (speedup 1.0000x reference)
#include <cuda_runtime.h>
#include <cuda_fp16.h>
#include <cstdint>

#define HEADS 4
#define F 128
#define MAXN 131072
#define MAXE 2097152
#define HPAD 136        // fp16 tile row stride (128 + 8) -> 272B, conflict-free

// ---------------- scratch (static device globals) ---------------------------
__device__ __half g_h[(size_t)MAXN * F];   // GEMM output h (fp16, both layers)
__device__ __half g_x2[(size_t)MAXN * F];  // layer-1 output / layer-2 input (fp16)
__device__ float g_as[MAXN * HEADS];       // alpha_src per node/head (fp32)
__device__ float g_ad[MAXN * HEADS];       // alpha_dst per node/head (fp32)
__device__ int   g_deg[MAXN];
__device__ int   g_rowptr[MAXN];
__device__ int   g_cursor[MAXN];
__device__ int   g_blksum[256];
__device__ int   g_csr_src[MAXE];

__device__ __forceinline__ float leaky_exp(float x) {
    float l = x > 0.f ? x : 0.2f * x;
    return __expf(l);
}

__device__ __forceinline__ void red_add1(int* p) {
    asm volatile("red.global.add.u32 [%0], 1;" :: "l"(p) : "memory");
}

// load 4 fp16 (8B) -> float4
__device__ __forceinline__ float4 load_h4(const __half* p) {
    uint2 raw = __ldg((const uint2*)p);
    __half2 h0 = *reinterpret_cast<__half2*>(&raw.x);
    __half2 h1 = *reinterpret_cast<__half2*>(&raw.y);
    float2 f0 = __half22float2(h0);
    float2 f1 = __half22float2(h1);
    return make_float4(f0.x, f0.y, f1.x, f1.y);
}

// ---------------- CSR build -------------------------------------------------
// degree count: no return value needed -> REDG (red.global.add), 4 edges/thr
__global__ void deg_kernel(const int* __restrict__ ei, int E) {
    int i = (blockIdx.x * blockDim.x + threadIdx.x) * 4;
    const int* dst = ei + E;
    if (i + 4 <= E) {
        int d0 = __ldg(dst + i);
        int d1 = __ldg(dst + i + 1);
        int d2 = __ldg(dst + i + 2);
        int d3 = __ldg(dst + i + 3);
        red_add1(&g_deg[d0]);
        red_add1(&g_deg[d1]);
        red_add1(&g_deg[d2]);
        red_add1(&g_deg[d3]);
    } else {
        for (; i < E; ++i) red_add1(&g_deg[__ldg(dst + i)]);
    }
}

__global__ void scan1_kernel(int N) {
    __shared__ int warp_sums[32];
    int t = threadIdx.x, b = blockIdx.x;
    int i = b * 1024 + t;
    int v = (i < N) ? g_deg[i] : 0;
    int x = v;
#pragma unroll
    for (int off = 1; off < 32; off <<= 1) {
        int y = __shfl_up_sync(0xffffffffu, x, off);
        if ((t & 31) >= off) x += y;
    }
    if ((t & 31) == 31) warp_sums[t >> 5] = x;
    __syncthreads();
    if (t < 32) {
        int w = warp_sums[t];
#pragma unroll
        for (int off = 1; off < 32; off <<= 1) {
            int y = __shfl_up_sync(0xffffffffu, w, off);
            if (t >= off) w += y;
        }
        warp_sums[t] = w;
    }
    __syncthreads();
    int incl = x + ((t >> 5) ? warp_sums[(t >> 5) - 1] : 0);
    if (i < N) g_rowptr[i] = incl - v;
    if (t == 1023) g_blksum[b] = incl;
}

__global__ void scan3_kernel(int N) {
    __shared__ int s_off;
    int b = blockIdx.x, t = threadIdx.x;
    if (t < 32) {
        int sum = 0;
        for (int j = t; j < b; j += 32) sum += g_blksum[j];
#pragma unroll
        for (int off = 16; off; off >>= 1)
            sum += __shfl_xor_sync(0xffffffffu, sum, off);
        if (t == 0) s_off = sum;
    }
    __syncthreads();
    int i = b * 1024 + t;
    if (i < N) {
        int r = g_rowptr[i] + s_off;
        g_rowptr[i] = r;
        g_cursor[i] = r;
    }
}

__global__ void scatter_kernel(const int* __restrict__ ei, int E) {
    int i = blockIdx.x * blockDim.x + threadIdx.x;
    if (i >= E) return;
    int s = __ldg(ei + i);
    int d = __ldg(ei + E + i);
    int pos = atomicAdd(&g_cursor[d], 1);
    g_csr_src[pos] = s;
}

// ---------------- fp16 HMMA GEMM (m16n8k16 + ldmatrix) + fused alphas -------
template <typename T>
__global__ void __launch_bounds__(256, 2)
gemm_fp16_kernel(const T* __restrict__ X, const float* __restrict__ Wm,
                 const float* __restrict__ a_s, const float* __restrict__ a_d,
                 int N) {
    extern __shared__ __half sm[];
    __half* Xs = sm;                   // [128][HPAD]
    __half* Ws = sm + 128 * HPAD;      // [128][HPAD]  (W[k][n], row-major k)
    const int tid = threadIdx.x;
    const int row0 = blockIdx.x * 128;

#pragma unroll
    for (int it = 0; it < 16; ++it) {
        int idx = it * 256 + tid;        // 0..4095
        int r = idx >> 5;                // row (X) / k (W), 0..127
        int q = idx & 31;                // 4-elem slot
        int gr = row0 + r;
        uint2 xpack = make_uint2(0u, 0u);
        if (gr < N) {
            if constexpr (sizeof(T) == 4) {
                float4 v = *(const float4*)&X[(size_t)gr * F + q * 4];
                __half2 p0 = __floats2half2_rn(v.x, v.y);
                __half2 p1 = __floats2half2_rn(v.z, v.w);
                xpack.x = *reinterpret_cast<uint32_t*>(&p0);
                xpack.y = *reinterpret_cast<uint32_t*>(&p1);
            } else {
                xpack = *(const uint2*)&X[(size_t)gr * F + q * 4];
            }
        }
        *(uint2*)&Xs[r * HPAD + q * 4] = xpack;

        float4 wv = *(const float4*)&Wm[(size_t)idx * 4];  // = W[r][q*4..+3]
        __half2 w0 = __floats2half2_rn(wv.x, wv.y);
        __half2 w1 = __floats2half2_rn(wv.z, wv.w);
        uint2 wpack;
        wpack.x = *reinterpret_cast<uint32_t*>(&w0);
        wpack.y = *reinterpret_cast<uint32_t*>(&w1);
        *(uint2*)&Ws[r * HPAD + q * 4] = wpack;
    }
    __syncthreads();

    const int w = tid >> 5, lane = tid & 31;
    const int g = lane >> 2, q = lane & 3;
    const int mrow = (w >> 1) * 32;
    const int cb = (w & 1) * 64;
    const int sel = lane >> 3, li = lane & 7;

    float acc[2][8][4];
#pragma unroll
    for (int mt = 0; mt < 2; ++mt)
#pragma unroll
        for (int j = 0; j < 8; ++j)
#pragma unroll
            for (int t = 0; t < 4; ++t) acc[mt][j][t] = 0.f;

    uint32_t xu = (uint32_t)__cvta_generic_to_shared(Xs);
    uint32_t wu = (uint32_t)__cvta_generic_to_shared(Ws);

    uint32_t aaddr[2], baddr[4];
#pragma unroll
    for (int mt = 0; mt < 2; ++mt)
        aaddr[mt] = xu + (uint32_t)(((mrow + mt * 16 + (sel & 1) * 8 + li) * HPAD
                                     + (sel >> 1) * 8) * 2);
#pragma unroll
    for (int p = 0; p < 4; ++p)
        baddr[p] = wu + (uint32_t)((((sel & 1) * 8 + li) * HPAD
                                    + cb + p * 16 + (sel >> 1) * 8) * 2);

#pragma unroll
    for (int ks = 0; ks < 8; ++ks) {
        uint32_t a[2][4];
#pragma unroll
        for (int mt = 0; mt < 2; ++mt) {
            asm volatile(
                "ldmatrix.sync.aligned.m8n8.x4.shared.b16 {%0,%1,%2,%3}, [%4];"
                : "=r"(a[mt][0]), "=r"(a[mt][1]), "=r"(a[mt][2]), "=r"(a[mt][3])
                : "r"(aaddr[mt]));
            aaddr[mt] += 32;                 // +16 halves along k
        }
        uint32_t b[4][4];
#pragma unroll
        for (int p = 0; p < 4; ++p) {
            asm volatile(
                "ldmatrix.sync.aligned.m8n8.x4.trans.shared.b16 {%0,%1,%2,%3}, [%4];"
                : "=r"(b[p][0]), "=r"(b[p][1]), "=r"(b[p][2]), "=r"(b[p][3])
                : "r"(baddr[p]));
            baddr[p] += 16 * HPAD * 2;       // +16 k rows
        }
#pragma unroll
        for (int j = 0; j < 8; ++j) {
            uint32_t b0 = b[j >> 1][(j & 1) * 2];
            uint32_t b1 = b[j >> 1][(j & 1) * 2 + 1];
#pragma unroll
            for (int mt = 0; mt < 2; ++mt) {
                asm volatile(
                    "mma.sync.aligned.m16n8k16.row.col.f32.f16.f16.f32 "
                    "{%0,%1,%2,%3}, {%4,%5,%6,%7}, {%8,%9}, {%0,%1,%2,%3};"
                    : "+f"(acc[mt][j][0]), "+f"(acc[mt][j][1]),
                      "+f"(acc[mt][j][2]), "+f"(acc[mt][j][3])
                    : "r"(a[mt][0]), "r"(a[mt][1]), "r"(a[mt][2]), "r"(a[mt][3]),
                      "r"(b0), "r"(b1));
            }
        }
    }

    // ---- epilogue: store h as fp16 + fused alpha partials (fp32 acc) -------
    float pa[4][2] = {{0.f, 0.f}, {0.f, 0.f}, {0.f, 0.f}, {0.f, 0.f}};
    float pd[4][2] = {{0.f, 0.f}, {0.f, 0.f}, {0.f, 0.f}, {0.f, 0.f}};
#pragma unroll
    for (int mt = 0; mt < 2; ++mt) {
#pragma unroll
        for (int j = 0; j < 8; ++j) {
            int col = cb + j * 8 + q * 2;
            float as0 = __ldg(&a_s[col]), as1 = __ldg(&a_s[col + 1]);
            float ad0 = __ldg(&a_d[col]), ad1 = __ldg(&a_d[col + 1]);
            int hh = j >> 2;
            float2 lo = make_float2(acc[mt][j][0], acc[mt][j][1]);  // row g
            float2 hi = make_float2(acc[mt][j][2], acc[mt][j][3]);  // row g+8
            pa[mt * 2 + 0][hh] += lo.x * as0 + lo.y * as1;
            pd[mt * 2 + 0][hh] += lo.x * ad0 + lo.y * ad1;
            pa[mt * 2 + 1][hh] += hi.x * as0 + hi.y * as1;
            pd[mt * 2 + 1][hh] += hi.x * ad0 + hi.y * ad1;
            int r_lo = row0 + mrow + mt * 16 + g;
            if (r_lo < N)
                *(__half2*)&g_h[(size_t)r_lo * F + col] = __floats2half2_rn(lo.x, lo.y);
            if (r_lo + 8 < N)
                *(__half2*)&g_h[(size_t)(r_lo + 8) * F + col] = __floats2half2_rn(hi.x, hi.y);
        }
    }
#pragma unroll
    for (int off = 1; off <= 2; off <<= 1) {
#pragma unroll
        for (int s = 0; s < 4; ++s)
#pragma unroll
            for (int hh = 0; hh < 2; ++hh) {
                pa[s][hh] += __shfl_xor_sync(0xffffffffu, pa[s][hh], off);
                pd[s][hh] += __shfl_xor_sync(0xffffffffu, pd[s][hh], off);
            }
    }
    if (q == 0) {
        int head_base = (w & 1) * 2;
#pragma unroll
        for (int s = 0; s < 4; ++s) {
            int mt = s >> 1, rh = s & 1;
            int row = row0 + mrow + mt * 16 + rh * 8 + g;
            if (row < N) {
#pragma unroll
                for (int hh = 0; hh < 2; ++hh) {
                    g_as[row * HEADS + head_base + hh] = pa[s][hh];
                    g_ad[row * HEADS + head_base + hh] = pd[s][hh];
                }
            }
        }
    }
}

// ---------------- CSR aggregation (warp per dst node, 4-way pipelined) ------
template <int LAYER>
__global__ void aggregate_kernel(const float* __restrict__ bias,
                                 float* __restrict__ out, int N, int write_splits) {
    int n = (blockIdx.x * blockDim.x + threadIdx.x) >> 5;
    int lane = threadIdx.x & 31;
    if (n >= N) return;
    int head = lane >> 3;
    int c = lane * 4;

    float adh = __ldg(&g_ad[n * HEADS + head]);
    float4 acc = make_float4(0.f, 0.f, 0.f, 0.f);
    float den = 0.f;

    int e = __ldg(&g_rowptr[n]);
    int end = __ldg(&g_cursor[n]);     // rowptr + deg after scatter

    for (; e + 4 <= end; e += 4) {
        int s0 = __ldg(&g_csr_src[e]);
        int s1 = __ldg(&g_csr_src[e + 1]);
        int s2 = __ldg(&g_csr_src[e + 2]);
        int s3 = __ldg(&g_csr_src[e + 3]);
        float as0 = __ldg(&g_as[s0 * HEADS + head]);
        float as1 = __ldg(&g_as[s1 * HEADS + head]);
        float as2 = __ldg(&g_as[s2 * HEADS + head]);
        float as3 = __ldg(&g_as[s3 * HEADS + head]);
        float4 h0 = load_h4(&g_h[(size_t)s0 * F + c]);
        float4 h1 = load_h4(&g_h[(size_t)s1 * F + c]);
        float4 h2 = load_h4(&g_h[(size_t)s2 * F + c]);
        float4 h3 = load_h4(&g_h[(size_t)s3 * F + c]);
        float w0 = leaky_exp(as0 + adh);
        float w1 = leaky_exp(as1 + adh);
        float w2 = leaky_exp(as2 + adh);
        float w3 = leaky_exp(as3 + adh);
        den += (w0 + w1) + (w2 + w3);
        acc.x = fmaf(w0, h0.x, fmaf(w1, h1.x, fmaf(w2, h2.x, fmaf(w3, h3.x, acc.x))));
        acc.y = fmaf(w0, h0.y, fmaf(w1, h1.y, fmaf(w2, h2.y, fmaf(w3, h3.y, acc.y))));
        acc.z = fmaf(w0, h0.z, fmaf(w1, h1.z, fmaf(w2, h2.z, fmaf(w3, h3.z, acc.z))));
        acc.w = fmaf(w0, h0.w, fmaf(w1, h1.w, fmaf(w2, h2.w, fmaf(w3, h3.w, acc.w))));
    }
    for (; e < end; ++e) {
        int s0 = __ldg(&g_csr_src[e]);
        float as0 = __ldg(&g_as[s0 * HEADS + head]);
        float4 h0 = load_h4(&g_h[(size_t)s0 * F + c]);
        float w0 = leaky_exp(as0 + adh);
        den += w0;
        acc.x = fmaf(w0, h0.x, acc.x);
        acc.y = fmaf(w0, h0.y, acc.y);
        acc.z = fmaf(w0, h0.z, acc.z);
        acc.w = fmaf(w0, h0.w, acc.w);
    }

    // self-loop
    float ws = leaky_exp(__ldg(&g_as[n * HEADS + head]) + adh);
    float4 hv = load_h4(&g_h[(size_t)n * F + c]);
    den += ws;
    acc.x = fmaf(ws, hv.x, acc.x);
    acc.y = fmaf(ws, hv.y, acc.y);
    acc.z = fmaf(ws, hv.z, acc.z);
    acc.w = fmaf(ws, hv.w, acc.w);

    float inv = 1.f / (den + 1e-16f);
    float4 bb = *(const float4*)&bias[c];
    float4 v;
    v.x = acc.x * inv + bb.x;
    v.y = acc.y * inv + bb.y;
    v.z = acc.z * inv + bb.z;
    v.w = acc.w * inv + bb.w;

    if (LAYER == 1) {
        v.x = v.x > 0.f ? v.x : expm1f(v.x);
        v.y = v.y > 0.f ? v.y : expm1f(v.y);
        v.z = v.z > 0.f ? v.z : expm1f(v.z);
        v.w = v.w > 0.f ? v.w : expm1f(v.w);
        uint2 packed;
        *reinterpret_cast<__half2*>(&packed.x) = __floats2half2_rn(v.x, v.y);
        *reinterpret_cast<__half2*>(&packed.y) = __floats2half2_rn(v.z, v.w);
        *(uint2*)&g_x2[(size_t)n * F + c] = packed;
    } else {
        *(float4*)&out[(size_t)n * F + c] = v;
        if (write_splits) {
            int off = c & 31;
            *(float4*)&out[(size_t)N * F + (size_t)head * N * 32 + (size_t)n * 32 + off] = v;
        }
    }
}

// ---------------- launch ----------------------------------------------------
// Side stream + events (lazily created on the uncaptured correctness call;
// captured work is identical on every call; no device memory allocated).
static cudaStream_t g_s2 = nullptr;
static cudaEvent_t g_ev_fork = nullptr, g_ev_join = nullptr;

extern "C" void kernel_launch(void* const* d_in, const int* in_sizes, int n_in,
                              void* d_out, int out_size) {
    const float* x   = (const float*)d_in[0];
    const int*   ei  = (const int*)d_in[1];
    const float* W1  = (const float*)d_in[2];
    const float* as1 = (const float*)d_in[3];
    const float* ad1 = (const float*)d_in[4];
    const float* b1  = (const float*)d_in[5];
    const float* W2  = (const float*)d_in[6];
    const float* as2 = (const float*)d_in[7];
    const float* ad2 = (const float*)d_in[8];
    const float* b2  = (const float*)d_in[9];

    int N = in_sizes[0] / F;
    int E = in_sizes[1] / 2;
    float* out = (float*)d_out;
    int write_splits = (out_size >= N * F * 2) ? 1 : 0;

    if (!g_s2) {
        cudaStreamCreateWithFlags(&g_s2, cudaStreamNonBlocking);
        cudaEventCreateWithFlags(&g_ev_fork, cudaEventDisableTiming);
        cudaEventCreateWithFlags(&g_ev_join, cudaEventDisableTiming);
    }

    __half* p_x2 = nullptr;
    cudaGetSymbolAddress((void**)&p_x2, g_x2);
    int* p_deg = nullptr;
    cudaGetSymbolAddress((void**)&p_deg, g_deg);

    const int SMEM_BYTES = 2 * 128 * HPAD * 2;   // Xs + Ws, fp16
    cudaFuncSetAttribute(gemm_fp16_kernel<float>,
                         cudaFuncAttributeMaxDynamicSharedMemorySize, SMEM_BYTES);
    cudaFuncSetAttribute(gemm_fp16_kernel<__half>,
                         cudaFuncAttributeMaxDynamicSharedMemorySize, SMEM_BYTES);

    int gb = (N + 127) / 128;
    int wb = (N * 32 + 255) / 256;
    int nb1024 = (N + 1023) / 1024;
    int eb1 = (E + 255) / 256;           // 1 edge/thread
    int eb4 = (E + 1023) / 1024;         // 4 edges/thread

    // fork: gemm1 on side stream, CSR build on default stream
    cudaEventRecord(g_ev_fork, 0);
    cudaStreamWaitEvent(g_s2, g_ev_fork, 0);

    cudaMemsetAsync(p_deg, 0, (size_t)N * sizeof(int), 0);
    deg_kernel<<<eb4, 256>>>(ei, E);
    scan1_kernel<<<nb1024, 1024>>>(N);
    scan3_kernel<<<nb1024, 1024>>>(N);
    scatter_kernel<<<eb1, 256>>>(ei, E);                 // #4 (profiled)

    gemm_fp16_kernel<float><<<gb, 256, SMEM_BYTES, g_s2>>>(x, W1, as1, ad1, N);
    cudaEventRecord(g_ev_join, g_s2);
    cudaStreamWaitEvent(0, g_ev_join, 0);   // agg1 needs CSR + gemm1

    // ---- layer 1 aggregate, layer 2 ----
    aggregate_kernel<1><<<wb, 256>>>(b1, out, N, 0);
    gemm_fp16_kernel<__half><<<gb, 256, SMEM_BYTES>>>(p_x2, W2, as2, ad2, N);
    aggregate_kernel<2><<<wb, 256>>>(b2, out, N, write_splits);
}

// round 11
// speedup vs baseline: 1.4315x; 1.4315x over previous
#include <cuda_runtime.h>
#include <cuda_fp16.h>
#include <cstdint>

#define HEADS 4
#define F 128
#define MAXN 131072
#define MAXE 2097152
#define HPAD 136        // fp16 tile row stride (128 + 8) -> 272B, conflict-free

// ---------------- scratch (static device globals) ---------------------------
__device__ __half g_h[(size_t)MAXN * F];   // GEMM output h (fp16, both layers)
__device__ __half g_x2[(size_t)MAXN * F];  // layer-1 output / layer-2 input (fp16)
__device__ float g_as[MAXN * HEADS];       // alpha_src per node/head (fp32)
__device__ float g_ad[MAXN * HEADS];       // alpha_dst per node/head (fp32)
__device__ int   g_deg[MAXN];
__device__ int   g_rowptr[MAXN];
__device__ int   g_cursor[MAXN];
__device__ int   g_blksum[256];
__device__ int   g_csr_src[MAXE];

__device__ __forceinline__ float leaky_exp(float x) {
    float l = x > 0.f ? x : 0.2f * x;
    return __expf(l);
}

// load 4 fp16 (8B) -> float4
__device__ __forceinline__ float4 load_h4(const __half* p) {
    uint2 raw = __ldg((const uint2*)p);
    __half2 h0 = *reinterpret_cast<__half2*>(&raw.x);
    __half2 h1 = *reinterpret_cast<__half2*>(&raw.y);
    float2 f0 = __half22float2(h0);
    float2 f1 = __half22float2(h1);
    return make_float4(f0.x, f0.y, f1.x, f1.y);
}

// ---------------- CSR build (4 edges/thread atomicAdd — R8 proven form) -----
__global__ void deg_kernel(const int* __restrict__ ei, int E) {
    int i = (blockIdx.x * blockDim.x + threadIdx.x) * 4;
    if (i + 4 <= E) {
        int d0 = __ldg(ei + E + i);
        int d1 = __ldg(ei + E + i + 1);
        int d2 = __ldg(ei + E + i + 2);
        int d3 = __ldg(ei + E + i + 3);
        atomicAdd(&g_deg[d0], 1);
        atomicAdd(&g_deg[d1], 1);
        atomicAdd(&g_deg[d2], 1);
        atomicAdd(&g_deg[d3], 1);
    } else {
        for (; i < E; ++i) atomicAdd(&g_deg[__ldg(ei + E + i)], 1);
    }
}

__global__ void scan1_kernel(int N) {
    __shared__ int warp_sums[32];
    int t = threadIdx.x, b = blockIdx.x;
    int i = b * 1024 + t;
    int v = (i < N) ? g_deg[i] : 0;
    int x = v;
#pragma unroll
    for (int off = 1; off < 32; off <<= 1) {
        int y = __shfl_up_sync(0xffffffffu, x, off);
        if ((t & 31) >= off) x += y;
    }
    if ((t & 31) == 31) warp_sums[t >> 5] = x;
    __syncthreads();
    if (t < 32) {
        int w = warp_sums[t];
#pragma unroll
        for (int off = 1; off < 32; off <<= 1) {
            int y = __shfl_up_sync(0xffffffffu, w, off);
            if (t >= off) w += y;
        }
        warp_sums[t] = w;
    }
    __syncthreads();
    int incl = x + ((t >> 5) ? warp_sums[(t >> 5) - 1] : 0);
    if (i < N) g_rowptr[i] = incl - v;
    if (t == 1023) g_blksum[b] = incl;
}

__global__ void scan3_kernel(int N) {
    __shared__ int s_off;
    int b = blockIdx.x, t = threadIdx.x;
    if (t < 32) {
        int sum = 0;
        for (int j = t; j < b; j += 32) sum += g_blksum[j];
#pragma unroll
        for (int off = 16; off; off >>= 1)
            sum += __shfl_xor_sync(0xffffffffu, sum, off);
        if (t == 0) s_off = sum;
    }
    __syncthreads();
    int i = b * 1024 + t;
    if (i < N) {
        int r = g_rowptr[i] + s_off;
        g_rowptr[i] = r;
        g_cursor[i] = r;
    }
}

__global__ void scatter_kernel(const int* __restrict__ ei, int E) {
    int i = (blockIdx.x * blockDim.x + threadIdx.x) * 4;
    if (i + 4 <= E) {
        int s0 = __ldg(ei + i),     s1 = __ldg(ei + i + 1);
        int s2 = __ldg(ei + i + 2), s3 = __ldg(ei + i + 3);
        int d0 = __ldg(ei + E + i),     d1 = __ldg(ei + E + i + 1);
        int d2 = __ldg(ei + E + i + 2), d3 = __ldg(ei + E + i + 3);
        int p0 = atomicAdd(&g_cursor[d0], 1);
        int p1 = atomicAdd(&g_cursor[d1], 1);
        int p2 = atomicAdd(&g_cursor[d2], 1);
        int p3 = atomicAdd(&g_cursor[d3], 1);
        g_csr_src[p0] = s0;
        g_csr_src[p1] = s1;
        g_csr_src[p2] = s2;
        g_csr_src[p3] = s3;
    } else {
        for (; i < E; ++i) {
            int s = __ldg(ei + i);
            int d = __ldg(ei + E + i);
            int pos = atomicAdd(&g_cursor[d], 1);
            g_csr_src[pos] = s;
        }
    }
}

// ---------------- fp16 HMMA GEMM (m16n8k16 + ldmatrix) + fused alphas -------
template <typename T>
__global__ void __launch_bounds__(256, 2)
gemm_fp16_kernel(const T* __restrict__ X, const float* __restrict__ Wm,
                 const float* __restrict__ a_s, const float* __restrict__ a_d,
                 int N) {
    extern __shared__ __half sm[];
    __half* Xs = sm;                   // [128][HPAD]
    __half* Ws = sm + 128 * HPAD;      // [128][HPAD]  (W[k][n], row-major k)
    const int tid = threadIdx.x;
    const int row0 = blockIdx.x * 128;

#pragma unroll
    for (int it = 0; it < 16; ++it) {
        int idx = it * 256 + tid;        // 0..4095
        int r = idx >> 5;                // row (X) / k (W), 0..127
        int q = idx & 31;                // 4-elem slot
        int gr = row0 + r;
        uint2 xpack = make_uint2(0u, 0u);
        if (gr < N) {
            if constexpr (sizeof(T) == 4) {
                float4 v = *(const float4*)&X[(size_t)gr * F + q * 4];
                __half2 p0 = __floats2half2_rn(v.x, v.y);
                __half2 p1 = __floats2half2_rn(v.z, v.w);
                xpack.x = *reinterpret_cast<uint32_t*>(&p0);
                xpack.y = *reinterpret_cast<uint32_t*>(&p1);
            } else {
                xpack = *(const uint2*)&X[(size_t)gr * F + q * 4];
            }
        }
        *(uint2*)&Xs[r * HPAD + q * 4] = xpack;

        float4 wv = *(const float4*)&Wm[(size_t)idx * 4];  // = W[r][q*4..+3]
        __half2 w0 = __floats2half2_rn(wv.x, wv.y);
        __half2 w1 = __floats2half2_rn(wv.z, wv.w);
        uint2 wpack;
        wpack.x = *reinterpret_cast<uint32_t*>(&w0);
        wpack.y = *reinterpret_cast<uint32_t*>(&w1);
        *(uint2*)&Ws[r * HPAD + q * 4] = wpack;
    }
    __syncthreads();

    const int w = tid >> 5, lane = tid & 31;
    const int g = lane >> 2, q = lane & 3;
    const int mrow = (w >> 1) * 32;
    const int cb = (w & 1) * 64;
    const int sel = lane >> 3, li = lane & 7;

    float acc[2][8][4];
#pragma unroll
    for (int mt = 0; mt < 2; ++mt)
#pragma unroll
        for (int j = 0; j < 8; ++j)
#pragma unroll
            for (int t = 0; t < 4; ++t) acc[mt][j][t] = 0.f;

    uint32_t xu = (uint32_t)__cvta_generic_to_shared(Xs);
    uint32_t wu = (uint32_t)__cvta_generic_to_shared(Ws);

    uint32_t aaddr[2], baddr[4];
#pragma unroll
    for (int mt = 0; mt < 2; ++mt)
        aaddr[mt] = xu + (uint32_t)(((mrow + mt * 16 + (sel & 1) * 8 + li) * HPAD
                                     + (sel >> 1) * 8) * 2);
#pragma unroll
    for (int p = 0; p < 4; ++p)
        baddr[p] = wu + (uint32_t)((((sel & 1) * 8 + li) * HPAD
                                    + cb + p * 16 + (sel >> 1) * 8) * 2);

#pragma unroll
    for (int ks = 0; ks < 8; ++ks) {
        uint32_t a[2][4];
#pragma unroll
        for (int mt = 0; mt < 2; ++mt) {
            asm volatile(
                "ldmatrix.sync.aligned.m8n8.x4.shared.b16 {%0,%1,%2,%3}, [%4];"
                : "=r"(a[mt][0]), "=r"(a[mt][1]), "=r"(a[mt][2]), "=r"(a[mt][3])
                : "r"(aaddr[mt]));
            aaddr[mt] += 32;                 // +16 halves along k
        }
        uint32_t b[4][4];
#pragma unroll
        for (int p = 0; p < 4; ++p) {
            asm volatile(
                "ldmatrix.sync.aligned.m8n8.x4.trans.shared.b16 {%0,%1,%2,%3}, [%4];"
                : "=r"(b[p][0]), "=r"(b[p][1]), "=r"(b[p][2]), "=r"(b[p][3])
                : "r"(baddr[p]));
            baddr[p] += 16 * HPAD * 2;       // +16 k rows
        }
#pragma unroll
        for (int j = 0; j < 8; ++j) {
            uint32_t b0 = b[j >> 1][(j & 1) * 2];
            uint32_t b1 = b[j >> 1][(j & 1) * 2 + 1];
#pragma unroll
            for (int mt = 0; mt < 2; ++mt) {
                asm volatile(
                    "mma.sync.aligned.m16n8k16.row.col.f32.f16.f16.f32 "
                    "{%0,%1,%2,%3}, {%4,%5,%6,%7}, {%8,%9}, {%0,%1,%2,%3};"
                    : "+f"(acc[mt][j][0]), "+f"(acc[mt][j][1]),
                      "+f"(acc[mt][j][2]), "+f"(acc[mt][j][3])
                    : "r"(a[mt][0]), "r"(a[mt][1]), "r"(a[mt][2]), "r"(a[mt][3]),
                      "r"(b0), "r"(b1));
            }
        }
    }

    // ---- epilogue: store h as fp16 + fused alpha partials (fp32 acc) -------
    float pa[4][2] = {{0.f, 0.f}, {0.f, 0.f}, {0.f, 0.f}, {0.f, 0.f}};
    float pd[4][2] = {{0.f, 0.f}, {0.f, 0.f}, {0.f, 0.f}, {0.f, 0.f}};
#pragma unroll
    for (int mt = 0; mt < 2; ++mt) {
#pragma unroll
        for (int j = 0; j < 8; ++j) {
            int col = cb + j * 8 + q * 2;
            float as0 = __ldg(&a_s[col]), as1 = __ldg(&a_s[col + 1]);
            float ad0 = __ldg(&a_d[col]), ad1 = __ldg(&a_d[col + 1]);
            int hh = j >> 2;
            float2 lo = make_float2(acc[mt][j][0], acc[mt][j][1]);  // row g
            float2 hi = make_float2(acc[mt][j][2], acc[mt][j][3]);  // row g+8
            pa[mt * 2 + 0][hh] += lo.x * as0 + lo.y * as1;
            pd[mt * 2 + 0][hh] += lo.x * ad0 + lo.y * ad1;
            pa[mt * 2 + 1][hh] += hi.x * as0 + hi.y * as1;
            pd[mt * 2 + 1][hh] += hi.x * ad0 + hi.y * ad1;
            int r_lo = row0 + mrow + mt * 16 + g;
            if (r_lo < N)
                *(__half2*)&g_h[(size_t)r_lo * F + col] = __floats2half2_rn(lo.x, lo.y);
            if (r_lo + 8 < N)
                *(__half2*)&g_h[(size_t)(r_lo + 8) * F + col] = __floats2half2_rn(hi.x, hi.y);
        }
    }
#pragma unroll
    for (int off = 1; off <= 2; off <<= 1) {
#pragma unroll
        for (int s = 0; s < 4; ++s)
#pragma unroll
            for (int hh = 0; hh < 2; ++hh) {
                pa[s][hh] += __shfl_xor_sync(0xffffffffu, pa[s][hh], off);
                pd[s][hh] += __shfl_xor_sync(0xffffffffu, pd[s][hh], off);
            }
    }
    if (q == 0) {
        int head_base = (w & 1) * 2;
#pragma unroll
        for (int s = 0; s < 4; ++s) {
            int mt = s >> 1, rh = s & 1;
            int row = row0 + mrow + mt * 16 + rh * 8 + g;
            if (row < N) {
#pragma unroll
                for (int hh = 0; hh < 2; ++hh) {
                    g_as[row * HEADS + head_base + hh] = pa[s][hh];
                    g_ad[row * HEADS + head_base + hh] = pd[s][hh];
                }
            }
        }
    }
}

// ---------------- CSR aggregation (warp per dst node, 4-way pipelined) ------
template <int LAYER>
__global__ void aggregate_kernel(const float* __restrict__ bias,
                                 float* __restrict__ out, int N, int write_splits) {
    int n = (blockIdx.x * blockDim.x + threadIdx.x) >> 5;
    int lane = threadIdx.x & 31;
    if (n >= N) return;
    int head = lane >> 3;
    int c = lane * 4;

    float adh = __ldg(&g_ad[n * HEADS + head]);
    float4 acc = make_float4(0.f, 0.f, 0.f, 0.f);
    float den = 0.f;

    int e = __ldg(&g_rowptr[n]);
    int end = e + __ldg(&g_deg[n]);

    for (; e + 4 <= end; e += 4) {
        int s0 = __ldg(&g_csr_src[e]);
        int s1 = __ldg(&g_csr_src[e + 1]);
        int s2 = __ldg(&g_csr_src[e + 2]);
        int s3 = __ldg(&g_csr_src[e + 3]);
        float as0 = __ldg(&g_as[s0 * HEADS + head]);
        float as1 = __ldg(&g_as[s1 * HEADS + head]);
        float as2 = __ldg(&g_as[s2 * HEADS + head]);
        float as3 = __ldg(&g_as[s3 * HEADS + head]);
        float4 h0 = load_h4(&g_h[(size_t)s0 * F + c]);
        float4 h1 = load_h4(&g_h[(size_t)s1 * F + c]);
        float4 h2 = load_h4(&g_h[(size_t)s2 * F + c]);
        float4 h3 = load_h4(&g_h[(size_t)s3 * F + c]);
        float w0 = leaky_exp(as0 + adh);
        float w1 = leaky_exp(as1 + adh);
        float w2 = leaky_exp(as2 + adh);
        float w3 = leaky_exp(as3 + adh);
        den += (w0 + w1) + (w2 + w3);
        acc.x = fmaf(w0, h0.x, fmaf(w1, h1.x, fmaf(w2, h2.x, fmaf(w3, h3.x, acc.x))));
        acc.y = fmaf(w0, h0.y, fmaf(w1, h1.y, fmaf(w2, h2.y, fmaf(w3, h3.y, acc.y))));
        acc.z = fmaf(w0, h0.z, fmaf(w1, h1.z, fmaf(w2, h2.z, fmaf(w3, h3.z, acc.z))));
        acc.w = fmaf(w0, h0.w, fmaf(w1, h1.w, fmaf(w2, h2.w, fmaf(w3, h3.w, acc.w))));
    }
    for (; e < end; ++e) {
        int s0 = __ldg(&g_csr_src[e]);
        float as0 = __ldg(&g_as[s0 * HEADS + head]);
        float4 h0 = load_h4(&g_h[(size_t)s0 * F + c]);
        float w0 = leaky_exp(as0 + adh);
        den += w0;
        acc.x = fmaf(w0, h0.x, acc.x);
        acc.y = fmaf(w0, h0.y, acc.y);
        acc.z = fmaf(w0, h0.z, acc.z);
        acc.w = fmaf(w0, h0.w, acc.w);
    }

    // self-loop
    float ws = leaky_exp(__ldg(&g_as[n * HEADS + head]) + adh);
    float4 hv = load_h4(&g_h[(size_t)n * F + c]);
    den += ws;
    acc.x = fmaf(ws, hv.x, acc.x);
    acc.y = fmaf(ws, hv.y, acc.y);
    acc.z = fmaf(ws, hv.z, acc.z);
    acc.w = fmaf(ws, hv.w, acc.w);

    float inv = 1.f / (den + 1e-16f);
    float4 bb = *(const float4*)&bias[c];
    float4 v;
    v.x = acc.x * inv + bb.x;
    v.y = acc.y * inv + bb.y;
    v.z = acc.z * inv + bb.z;
    v.w = acc.w * inv + bb.w;

    if (LAYER == 1) {
        v.x = v.x > 0.f ? v.x : expm1f(v.x);
        v.y = v.y > 0.f ? v.y : expm1f(v.y);
        v.z = v.z > 0.f ? v.z : expm1f(v.z);
        v.w = v.w > 0.f ? v.w : expm1f(v.w);
        uint2 packed;
        *reinterpret_cast<__half2*>(&packed.x) = __floats2half2_rn(v.x, v.y);
        *reinterpret_cast<__half2*>(&packed.y) = __floats2half2_rn(v.z, v.w);
        *(uint2*)&g_x2[(size_t)n * F + c] = packed;
    } else {
        *(float4*)&out[(size_t)n * F + c] = v;
        if (write_splits) {
            int off = c & 31;
            *(float4*)&out[(size_t)N * F + (size_t)head * N * 32 + (size_t)n * 32 + off] = v;
        }
    }
}

// ---------------- launch ----------------------------------------------------
// Side stream + events (lazily created on the uncaptured correctness call;
// captured work is identical on every call; no device memory allocated).
static cudaStream_t g_s2 = nullptr;
static cudaEvent_t g_ev_fork = nullptr, g_ev_join = nullptr;

extern "C" void kernel_launch(void* const* d_in, const int* in_sizes, int n_in,
                              void* d_out, int out_size) {
    const float* x   = (const float*)d_in[0];
    const int*   ei  = (const int*)d_in[1];
    const float* W1  = (const float*)d_in[2];
    const float* as1 = (const float*)d_in[3];
    const float* ad1 = (const float*)d_in[4];
    const float* b1  = (const float*)d_in[5];
    const float* W2  = (const float*)d_in[6];
    const float* as2 = (const float*)d_in[7];
    const float* ad2 = (const float*)d_in[8];
    const float* b2  = (const float*)d_in[9];

    int N = in_sizes[0] / F;
    int E = in_sizes[1] / 2;
    float* out = (float*)d_out;
    int write_splits = (out_size >= N * F * 2) ? 1 : 0;

    if (!g_s2) {
        cudaStreamCreateWithFlags(&g_s2, cudaStreamNonBlocking);
        cudaEventCreateWithFlags(&g_ev_fork, cudaEventDisableTiming);
        cudaEventCreateWithFlags(&g_ev_join, cudaEventDisableTiming);
    }

    __half* p_x2 = nullptr;
    cudaGetSymbolAddress((void**)&p_x2, g_x2);
    int* p_deg = nullptr;
    cudaGetSymbolAddress((void**)&p_deg, g_deg);

    const int SMEM_BYTES = 2 * 128 * HPAD * 2;   // Xs + Ws, fp16
    cudaFuncSetAttribute(gemm_fp16_kernel<float>,
                         cudaFuncAttributeMaxDynamicSharedMemorySize, SMEM_BYTES);
    cudaFuncSetAttribute(gemm_fp16_kernel<__half>,
                         cudaFuncAttributeMaxDynamicSharedMemorySize, SMEM_BYTES);

    int gb = (N + 127) / 128;
    int wb = (N * 32 + 255) / 256;
    int nb1024 = (N + 1023) / 1024;
    int eb4 = (E / 4 + 1 + 255) / 256;   // 4 edges/thread kernels

    // fork: gemm1 on side stream, CSR build on default stream
    cudaEventRecord(g_ev_fork, 0);
    cudaStreamWaitEvent(g_s2, g_ev_fork, 0);

    cudaMemsetAsync(p_deg, 0, (size_t)N * sizeof(int), 0);
    deg_kernel<<<eb4, 256>>>(ei, E);
    scan1_kernel<<<nb1024, 1024>>>(N);
    scan3_kernel<<<nb1024, 1024>>>(N);
    scatter_kernel<<<eb4, 256>>>(ei, E);                 // #4 (profiled)

    gemm_fp16_kernel<float><<<gb, 256, SMEM_BYTES, g_s2>>>(x, W1, as1, ad1, N);
    cudaEventRecord(g_ev_join, g_s2);
    cudaStreamWaitEvent(0, g_ev_join, 0);   // agg1 needs CSR + gemm1

    // ---- layer 1 aggregate, layer 2 ----
    aggregate_kernel<1><<<wb, 256>>>(b1, out, N, 0);
    gemm_fp16_kernel<__half><<<gb, 256, SMEM_BYTES>>>(p_x2, W2, as2, ad2, N);
    aggregate_kernel<2><<<wb, 256>>>(b2, out, N, write_splits);
}

// round 12
// speedup vs baseline: 1.5222x; 1.0634x over previous
#include <cuda_runtime.h>
#include <cuda_fp16.h>
#include <cstdint>

#define HEADS 4
#define F 128
#define MAXN 131072
#define MAXE 2097152
#define HPAD 136        // fp16 tile row stride (128 + 8) -> 272B, conflict-free

// ---------------- scratch (static device globals) ---------------------------
__device__ __half g_h[(size_t)MAXN * F];   // GEMM output h (fp16, both layers)
__device__ __half g_x2[(size_t)MAXN * F];  // layer-1 output / layer-2 input (fp16)
__device__ float g_as[MAXN * HEADS];       // alpha_src per node/head (fp32)
__device__ float g_ad[MAXN * HEADS];       // alpha_dst per node/head (fp32)
__device__ int   g_deg[MAXN];
__device__ int   g_rowptr[MAXN];
__device__ int   g_cursor[MAXN];
__device__ int   g_blksum[256];
__device__ int   g_csr_src[MAXE];

__device__ __forceinline__ float leaky_exp(float x) {
    float l = x > 0.f ? x : 0.2f * x;
    return __expf(l);
}

// load 4 fp16 (8B) -> float4
__device__ __forceinline__ float4 load_h4(const __half* p) {
    uint2 raw = __ldg((const uint2*)p);
    __half2 h0 = *reinterpret_cast<__half2*>(&raw.x);
    __half2 h1 = *reinterpret_cast<__half2*>(&raw.y);
    float2 f0 = __half22float2(h0);
    float2 f1 = __half22float2(h1);
    return make_float4(f0.x, f0.y, f1.x, f1.y);
}

// streaming (evict-first) stores: keep L2 for the h table
__device__ __forceinline__ void stcs4(float* p, float4 v) {
    asm volatile("st.global.cs.v4.f32 [%0], {%1,%2,%3,%4};"
                 :: "l"(p), "f"(v.x), "f"(v.y), "f"(v.z), "f"(v.w) : "memory");
}
__device__ __forceinline__ void stcs2u(uint2* p, uint2 v) {
    asm volatile("st.global.cs.v2.u32 [%0], {%1,%2};"
                 :: "l"(p), "r"(v.x), "r"(v.y) : "memory");
}

// ---------------- CSR build (4 edges/thread atomicAdd — R8 proven form) -----
__global__ void deg_kernel(const int* __restrict__ ei, int E) {
    int i = (blockIdx.x * blockDim.x + threadIdx.x) * 4;
    if (i + 4 <= E) {
        int d0 = __ldg(ei + E + i);
        int d1 = __ldg(ei + E + i + 1);
        int d2 = __ldg(ei + E + i + 2);
        int d3 = __ldg(ei + E + i + 3);
        atomicAdd(&g_deg[d0], 1);
        atomicAdd(&g_deg[d1], 1);
        atomicAdd(&g_deg[d2], 1);
        atomicAdd(&g_deg[d3], 1);
    } else {
        for (; i < E; ++i) atomicAdd(&g_deg[__ldg(ei + E + i)], 1);
    }
}

__global__ void scan1_kernel(int N) {
    __shared__ int warp_sums[32];
    int t = threadIdx.x, b = blockIdx.x;
    int i = b * 1024 + t;
    int v = (i < N) ? g_deg[i] : 0;
    int x = v;
#pragma unroll
    for (int off = 1; off < 32; off <<= 1) {
        int y = __shfl_up_sync(0xffffffffu, x, off);
        if ((t & 31) >= off) x += y;
    }
    if ((t & 31) == 31) warp_sums[t >> 5] = x;
    __syncthreads();
    if (t < 32) {
        int w = warp_sums[t];
#pragma unroll
        for (int off = 1; off < 32; off <<= 1) {
            int y = __shfl_up_sync(0xffffffffu, w, off);
            if (t >= off) w += y;
        }
        warp_sums[t] = w;
    }
    __syncthreads();
    int incl = x + ((t >> 5) ? warp_sums[(t >> 5) - 1] : 0);
    if (i < N) g_rowptr[i] = incl - v;
    if (t == 1023) g_blksum[b] = incl;
}

__global__ void scan3_kernel(int N) {
    __shared__ int s_off;
    int b = blockIdx.x, t = threadIdx.x;
    if (t < 32) {
        int sum = 0;
        for (int j = t; j < b; j += 32) sum += g_blksum[j];
#pragma unroll
        for (int off = 16; off; off >>= 1)
            sum += __shfl_xor_sync(0xffffffffu, sum, off);
        if (t == 0) s_off = sum;
    }
    __syncthreads();
    int i = b * 1024 + t;
    if (i < N) {
        int r = g_rowptr[i] + s_off;
        g_rowptr[i] = r;
        g_cursor[i] = r;
    }
}

__global__ void scatter_kernel(const int* __restrict__ ei, int E) {
    int i = (blockIdx.x * blockDim.x + threadIdx.x) * 4;
    if (i + 4 <= E) {
        int s0 = __ldg(ei + i),     s1 = __ldg(ei + i + 1);
        int s2 = __ldg(ei + i + 2), s3 = __ldg(ei + i + 3);
        int d0 = __ldg(ei + E + i),     d1 = __ldg(ei + E + i + 1);
        int d2 = __ldg(ei + E + i + 2), d3 = __ldg(ei + E + i + 3);
        int p0 = atomicAdd(&g_cursor[d0], 1);
        int p1 = atomicAdd(&g_cursor[d1], 1);
        int p2 = atomicAdd(&g_cursor[d2], 1);
        int p3 = atomicAdd(&g_cursor[d3], 1);
        g_csr_src[p0] = s0;
        g_csr_src[p1] = s1;
        g_csr_src[p2] = s2;
        g_csr_src[p3] = s3;
    } else {
        for (; i < E; ++i) {
            int s = __ldg(ei + i);
            int d = __ldg(ei + E + i);
            int pos = atomicAdd(&g_cursor[d], 1);
            g_csr_src[pos] = s;
        }
    }
}

// ---------------- fp16 HMMA GEMM (m16n8k16 + ldmatrix) + fused alphas -------
template <typename T>
__global__ void __launch_bounds__(256, 2)
gemm_fp16_kernel(const T* __restrict__ X, const float* __restrict__ Wm,
                 const float* __restrict__ a_s, const float* __restrict__ a_d,
                 int N) {
    extern __shared__ __half sm[];
    __half* Xs = sm;                   // [128][HPAD]
    __half* Ws = sm + 128 * HPAD;      // [128][HPAD]  (W[k][n], row-major k)
    const int tid = threadIdx.x;
    const int row0 = blockIdx.x * 128;

#pragma unroll
    for (int it = 0; it < 16; ++it) {
        int idx = it * 256 + tid;        // 0..4095
        int r = idx >> 5;                // row (X) / k (W), 0..127
        int q = idx & 31;                // 4-elem slot
        int gr = row0 + r;
        uint2 xpack = make_uint2(0u, 0u);
        if (gr < N) {
            if constexpr (sizeof(T) == 4) {
                // streaming read: x is read exactly once, don't cache it
                float4 v = __ldcs((const float4*)&X[(size_t)gr * F + q * 4]);
                __half2 p0 = __floats2half2_rn(v.x, v.y);
                __half2 p1 = __floats2half2_rn(v.z, v.w);
                xpack.x = *reinterpret_cast<uint32_t*>(&p0);
                xpack.y = *reinterpret_cast<uint32_t*>(&p1);
            } else {
                xpack = __ldcs((const uint2*)&X[(size_t)gr * F + q * 4]);
            }
        }
        *(uint2*)&Xs[r * HPAD + q * 4] = xpack;

        float4 wv = *(const float4*)&Wm[(size_t)idx * 4];  // = W[r][q*4..+3]
        __half2 w0 = __floats2half2_rn(wv.x, wv.y);
        __half2 w1 = __floats2half2_rn(wv.z, wv.w);
        uint2 wpack;
        wpack.x = *reinterpret_cast<uint32_t*>(&w0);
        wpack.y = *reinterpret_cast<uint32_t*>(&w1);
        *(uint2*)&Ws[r * HPAD + q * 4] = wpack;
    }
    __syncthreads();

    const int w = tid >> 5, lane = tid & 31;
    const int g = lane >> 2, q = lane & 3;
    const int mrow = (w >> 1) * 32;
    const int cb = (w & 1) * 64;
    const int sel = lane >> 3, li = lane & 7;

    float acc[2][8][4];
#pragma unroll
    for (int mt = 0; mt < 2; ++mt)
#pragma unroll
        for (int j = 0; j < 8; ++j)
#pragma unroll
            for (int t = 0; t < 4; ++t) acc[mt][j][t] = 0.f;

    uint32_t xu = (uint32_t)__cvta_generic_to_shared(Xs);
    uint32_t wu = (uint32_t)__cvta_generic_to_shared(Ws);

    uint32_t aaddr[2], baddr[4];
#pragma unroll
    for (int mt = 0; mt < 2; ++mt)
        aaddr[mt] = xu + (uint32_t)(((mrow + mt * 16 + (sel & 1) * 8 + li) * HPAD
                                     + (sel >> 1) * 8) * 2);
#pragma unroll
    for (int p = 0; p < 4; ++p)
        baddr[p] = wu + (uint32_t)((((sel & 1) * 8 + li) * HPAD
                                    + cb + p * 16 + (sel >> 1) * 8) * 2);

#pragma unroll
    for (int ks = 0; ks < 8; ++ks) {
        uint32_t a[2][4];
#pragma unroll
        for (int mt = 0; mt < 2; ++mt) {
            asm volatile(
                "ldmatrix.sync.aligned.m8n8.x4.shared.b16 {%0,%1,%2,%3}, [%4];"
                : "=r"(a[mt][0]), "=r"(a[mt][1]), "=r"(a[mt][2]), "=r"(a[mt][3])
                : "r"(aaddr[mt]));
            aaddr[mt] += 32;                 // +16 halves along k
        }
        uint32_t b[4][4];
#pragma unroll
        for (int p = 0; p < 4; ++p) {
            asm volatile(
                "ldmatrix.sync.aligned.m8n8.x4.trans.shared.b16 {%0,%1,%2,%3}, [%4];"
                : "=r"(b[p][0]), "=r"(b[p][1]), "=r"(b[p][2]), "=r"(b[p][3])
                : "r"(baddr[p]));
            baddr[p] += 16 * HPAD * 2;       // +16 k rows
        }
#pragma unroll
        for (int j = 0; j < 8; ++j) {
            uint32_t b0 = b[j >> 1][(j & 1) * 2];
            uint32_t b1 = b[j >> 1][(j & 1) * 2 + 1];
#pragma unroll
            for (int mt = 0; mt < 2; ++mt) {
                asm volatile(
                    "mma.sync.aligned.m16n8k16.row.col.f32.f16.f16.f32 "
                    "{%0,%1,%2,%3}, {%4,%5,%6,%7}, {%8,%9}, {%0,%1,%2,%3};"
                    : "+f"(acc[mt][j][0]), "+f"(acc[mt][j][1]),
                      "+f"(acc[mt][j][2]), "+f"(acc[mt][j][3])
                    : "r"(a[mt][0]), "r"(a[mt][1]), "r"(a[mt][2]), "r"(a[mt][3]),
                      "r"(b0), "r"(b1));
            }
        }
    }

    // ---- epilogue: store h as fp16 + fused alpha partials (fp32 acc) -------
    float pa[4][2] = {{0.f, 0.f}, {0.f, 0.f}, {0.f, 0.f}, {0.f, 0.f}};
    float pd[4][2] = {{0.f, 0.f}, {0.f, 0.f}, {0.f, 0.f}, {0.f, 0.f}};
#pragma unroll
    for (int mt = 0; mt < 2; ++mt) {
#pragma unroll
        for (int j = 0; j < 8; ++j) {
            int col = cb + j * 8 + q * 2;
            float as0 = __ldg(&a_s[col]), as1 = __ldg(&a_s[col + 1]);
            float ad0 = __ldg(&a_d[col]), ad1 = __ldg(&a_d[col + 1]);
            int hh = j >> 2;
            float2 lo = make_float2(acc[mt][j][0], acc[mt][j][1]);  // row g
            float2 hi = make_float2(acc[mt][j][2], acc[mt][j][3]);  // row g+8
            pa[mt * 2 + 0][hh] += lo.x * as0 + lo.y * as1;
            pd[mt * 2 + 0][hh] += lo.x * ad0 + lo.y * ad1;
            pa[mt * 2 + 1][hh] += hi.x * as0 + hi.y * as1;
            pd[mt * 2 + 1][hh] += hi.x * ad0 + hi.y * ad1;
            int r_lo = row0 + mrow + mt * 16 + g;
            if (r_lo < N)
                *(__half2*)&g_h[(size_t)r_lo * F + col] = __floats2half2_rn(lo.x, lo.y);
            if (r_lo + 8 < N)
                *(__half2*)&g_h[(size_t)(r_lo + 8) * F + col] = __floats2half2_rn(hi.x, hi.y);
        }
    }
#pragma unroll
    for (int off = 1; off <= 2; off <<= 1) {
#pragma unroll
        for (int s = 0; s < 4; ++s)
#pragma unroll
            for (int hh = 0; hh < 2; ++hh) {
                pa[s][hh] += __shfl_xor_sync(0xffffffffu, pa[s][hh], off);
                pd[s][hh] += __shfl_xor_sync(0xffffffffu, pd[s][hh], off);
            }
    }
    if (q == 0) {
        int head_base = (w & 1) * 2;
#pragma unroll
        for (int s = 0; s < 4; ++s) {
            int mt = s >> 1, rh = s & 1;
            int row = row0 + mrow + mt * 16 + rh * 8 + g;
            if (row < N) {
#pragma unroll
                for (int hh = 0; hh < 2; ++hh) {
                    g_as[row * HEADS + head_base + hh] = pa[s][hh];
                    g_ad[row * HEADS + head_base + hh] = pd[s][hh];
                }
            }
        }
    }
}

// ---------------- CSR aggregation (warp per dst node) -----------------------
// 64-thread blocks (2 warps) to cut CTA-tail imbalance from deg variance.
template <int LAYER>
__global__ void __launch_bounds__(64)
aggregate_kernel(const float* __restrict__ bias,
                 float* __restrict__ out, int N, int write_splits) {
    int n = (blockIdx.x * blockDim.x + threadIdx.x) >> 5;
    int lane = threadIdx.x & 31;
    if (n >= N) return;
    int head = lane >> 3;
    int c = lane * 4;

    float adh = __ldg(&g_ad[n * HEADS + head]);
    float4 acc = make_float4(0.f, 0.f, 0.f, 0.f);
    float den = 0.f;

    int e = __ldg(&g_rowptr[n]);
    int end = e + __ldg(&g_deg[n]);

    for (; e + 4 <= end; e += 4) {
        int s0 = __ldg(&g_csr_src[e]);
        int s1 = __ldg(&g_csr_src[e + 1]);
        int s2 = __ldg(&g_csr_src[e + 2]);
        int s3 = __ldg(&g_csr_src[e + 3]);
        float as0 = __ldg(&g_as[s0 * HEADS + head]);
        float as1 = __ldg(&g_as[s1 * HEADS + head]);
        float as2 = __ldg(&g_as[s2 * HEADS + head]);
        float as3 = __ldg(&g_as[s3 * HEADS + head]);
        float4 h0 = load_h4(&g_h[(size_t)s0 * F + c]);
        float4 h1 = load_h4(&g_h[(size_t)s1 * F + c]);
        float4 h2 = load_h4(&g_h[(size_t)s2 * F + c]);
        float4 h3 = load_h4(&g_h[(size_t)s3 * F + c]);
        float w0 = leaky_exp(as0 + adh);
        float w1 = leaky_exp(as1 + adh);
        float w2 = leaky_exp(as2 + adh);
        float w3 = leaky_exp(as3 + adh);
        den += (w0 + w1) + (w2 + w3);
        acc.x = fmaf(w0, h0.x, fmaf(w1, h1.x, fmaf(w2, h2.x, fmaf(w3, h3.x, acc.x))));
        acc.y = fmaf(w0, h0.y, fmaf(w1, h1.y, fmaf(w2, h2.y, fmaf(w3, h3.y, acc.y))));
        acc.z = fmaf(w0, h0.z, fmaf(w1, h1.z, fmaf(w2, h2.z, fmaf(w3, h3.z, acc.z))));
        acc.w = fmaf(w0, h0.w, fmaf(w1, h1.w, fmaf(w2, h2.w, fmaf(w3, h3.w, acc.w))));
    }
    for (; e < end; ++e) {
        int s0 = __ldg(&g_csr_src[e]);
        float as0 = __ldg(&g_as[s0 * HEADS + head]);
        float4 h0 = load_h4(&g_h[(size_t)s0 * F + c]);
        float w0 = leaky_exp(as0 + adh);
        den += w0;
        acc.x = fmaf(w0, h0.x, acc.x);
        acc.y = fmaf(w0, h0.y, acc.y);
        acc.z = fmaf(w0, h0.z, acc.z);
        acc.w = fmaf(w0, h0.w, acc.w);
    }

    // self-loop
    float ws = leaky_exp(__ldg(&g_as[n * HEADS + head]) + adh);
    float4 hv = load_h4(&g_h[(size_t)n * F + c]);
    den += ws;
    acc.x = fmaf(ws, hv.x, acc.x);
    acc.y = fmaf(ws, hv.y, acc.y);
    acc.z = fmaf(ws, hv.z, acc.z);
    acc.w = fmaf(ws, hv.w, acc.w);

    float inv = 1.f / (den + 1e-16f);
    float4 bb = *(const float4*)&bias[c];
    float4 v;
    v.x = acc.x * inv + bb.x;
    v.y = acc.y * inv + bb.y;
    v.z = acc.z * inv + bb.z;
    v.w = acc.w * inv + bb.w;

    if (LAYER == 1) {
        v.x = v.x > 0.f ? v.x : expm1f(v.x);
        v.y = v.y > 0.f ? v.y : expm1f(v.y);
        v.z = v.z > 0.f ? v.z : expm1f(v.z);
        v.w = v.w > 0.f ? v.w : expm1f(v.w);
        uint2 packed;
        *reinterpret_cast<__half2*>(&packed.x) = __floats2half2_rn(v.x, v.y);
        *reinterpret_cast<__half2*>(&packed.y) = __floats2half2_rn(v.z, v.w);
        stcs2u((uint2*)&g_x2[(size_t)n * F + c], packed);   // evict-first
    } else {
        stcs4(&out[(size_t)n * F + c], v);                  // evict-first
        if (write_splits) {
            int off = c & 31;
            stcs4(&out[(size_t)N * F + (size_t)head * N * 32 + (size_t)n * 32 + off], v);
        }
    }
}

// ---------------- launch ----------------------------------------------------
// Side stream + events (lazily created on the uncaptured correctness call;
// captured work is identical on every call; no device memory allocated).
static cudaStream_t g_s2 = nullptr;
static cudaEvent_t g_ev_fork = nullptr, g_ev_join = nullptr;

extern "C" void kernel_launch(void* const* d_in, const int* in_sizes, int n_in,
                              void* d_out, int out_size) {
    const float* x   = (const float*)d_in[0];
    const int*   ei  = (const int*)d_in[1];
    const float* W1  = (const float*)d_in[2];
    const float* as1 = (const float*)d_in[3];
    const float* ad1 = (const float*)d_in[4];
    const float* b1  = (const float*)d_in[5];
    const float* W2  = (const float*)d_in[6];
    const float* as2 = (const float*)d_in[7];
    const float* ad2 = (const float*)d_in[8];
    const float* b2  = (const float*)d_in[9];

    int N = in_sizes[0] / F;
    int E = in_sizes[1] / 2;
    float* out = (float*)d_out;
    int write_splits = (out_size >= N * F * 2) ? 1 : 0;

    if (!g_s2) {
        cudaStreamCreateWithFlags(&g_s2, cudaStreamNonBlocking);
        cudaEventCreateWithFlags(&g_ev_fork, cudaEventDisableTiming);
        cudaEventCreateWithFlags(&g_ev_join, cudaEventDisableTiming);
    }

    __half* p_x2 = nullptr;
    cudaGetSymbolAddress((void**)&p_x2, g_x2);
    int* p_deg = nullptr;
    cudaGetSymbolAddress((void**)&p_deg, g_deg);

    const int SMEM_BYTES = 2 * 128 * HPAD * 2;   // Xs + Ws, fp16
    cudaFuncSetAttribute(gemm_fp16_kernel<float>,
                         cudaFuncAttributeMaxDynamicSharedMemorySize, SMEM_BYTES);
    cudaFuncSetAttribute(gemm_fp16_kernel<__half>,
                         cudaFuncAttributeMaxDynamicSharedMemorySize, SMEM_BYTES);

    int gb = (N + 127) / 128;
    int wb64 = (N * 32 + 63) / 64;       // 64-thread aggregate blocks
    int nb1024 = (N + 1023) / 1024;
    int eb4 = (E / 4 + 1 + 255) / 256;   // 4 edges/thread kernels

    // fork: gemm1 on side stream, CSR build on default stream
    cudaEventRecord(g_ev_fork, 0);
    cudaStreamWaitEvent(g_s2, g_ev_fork, 0);

    cudaMemsetAsync(p_deg, 0, (size_t)N * sizeof(int), 0);
    deg_kernel<<<eb4, 256>>>(ei, E);
    scan1_kernel<<<nb1024, 1024>>>(N);
    scan3_kernel<<<nb1024, 1024>>>(N);
    scatter_kernel<<<eb4, 256>>>(ei, E);                 // #4 (profiled)

    gemm_fp16_kernel<float><<<gb, 256, SMEM_BYTES, g_s2>>>(x, W1, as1, ad1, N);
    cudaEventRecord(g_ev_join, g_s2);
    cudaStreamWaitEvent(0, g_ev_join, 0);   // agg1 needs CSR + gemm1

    // ---- layer 1 aggregate, layer 2 ----
    aggregate_kernel<1><<<wb64, 64>>>(b1, out, N, 0);
    gemm_fp16_kernel<__half><<<gb, 256, SMEM_BYTES>>>(p_x2, W2, as2, ad2, N);
    aggregate_kernel<2><<<wb64, 64>>>(b2, out, N, write_splits);
}

// round 13
// speedup vs baseline: 1.5640x; 1.0275x over previous
#include <cuda_runtime.h>
#include <cuda_fp16.h>
#include <cstdint>

#define HEADS 4
#define F 128
#define MAXN 131072
#define MAXE 2097152
#define HPAD 136        // fp16 tile row stride (128 + 8) -> 272B, conflict-free

// ---------------- scratch (static device globals) ---------------------------
__device__ __half g_h[(size_t)MAXN * F];   // GEMM output h (fp16, both layers)
__device__ __half g_x2[(size_t)MAXN * F];  // layer-1 output / layer-2 input (fp16)
__device__ float g_as[MAXN * HEADS];       // alpha_src per node/head (fp32)
__device__ float g_ad[MAXN * HEADS];       // alpha_dst per node/head (fp32)
__device__ int   g_deg[MAXN];
__device__ int   g_rowptr[MAXN];
__device__ int   g_cursor[MAXN];
__device__ int   g_blksum[256];
__device__ int   g_csr_src[MAXE];

__device__ __forceinline__ float leaky_exp(float x) {
    float l = x > 0.f ? x : 0.2f * x;
    return __expf(l);
}

// streaming (evict-first) stores: keep L2 for the h table
__device__ __forceinline__ void stcs4(float* p, float4 v) {
    asm volatile("st.global.cs.v4.f32 [%0], {%1,%2,%3,%4};"
                 :: "l"(p), "f"(v.x), "f"(v.y), "f"(v.z), "f"(v.w) : "memory");
}
__device__ __forceinline__ void stcs4u(uint4* p, uint4 v) {
    asm volatile("st.global.cs.v4.u32 [%0], {%1,%2,%3,%4};"
                 :: "l"(p), "r"(v.x), "r"(v.y), "r"(v.z), "r"(v.w) : "memory");
}

// ---------------- CSR build (4 edges/thread atomicAdd — R8 proven form) -----
__global__ void deg_kernel(const int* __restrict__ ei, int E) {
    int i = (blockIdx.x * blockDim.x + threadIdx.x) * 4;
    if (i + 4 <= E) {
        int d0 = __ldg(ei + E + i);
        int d1 = __ldg(ei + E + i + 1);
        int d2 = __ldg(ei + E + i + 2);
        int d3 = __ldg(ei + E + i + 3);
        atomicAdd(&g_deg[d0], 1);
        atomicAdd(&g_deg[d1], 1);
        atomicAdd(&g_deg[d2], 1);
        atomicAdd(&g_deg[d3], 1);
    } else {
        for (; i < E; ++i) atomicAdd(&g_deg[__ldg(ei + E + i)], 1);
    }
}

__global__ void scan1_kernel(int N) {
    __shared__ int warp_sums[32];
    int t = threadIdx.x, b = blockIdx.x;
    int i = b * 1024 + t;
    int v = (i < N) ? g_deg[i] : 0;
    int x = v;
#pragma unroll
    for (int off = 1; off < 32; off <<= 1) {
        int y = __shfl_up_sync(0xffffffffu, x, off);
        if ((t & 31) >= off) x += y;
    }
    if ((t & 31) == 31) warp_sums[t >> 5] = x;
    __syncthreads();
    if (t < 32) {
        int w = warp_sums[t];
#pragma unroll
        for (int off = 1; off < 32; off <<= 1) {
            int y = __shfl_up_sync(0xffffffffu, w, off);
            if (t >= off) w += y;
        }
        warp_sums[t] = w;
    }
    __syncthreads();
    int incl = x + ((t >> 5) ? warp_sums[(t >> 5) - 1] : 0);
    if (i < N) g_rowptr[i] = incl - v;
    if (t == 1023) g_blksum[b] = incl;
}

__global__ void scan3_kernel(int N) {
    __shared__ int s_off;
    int b = blockIdx.x, t = threadIdx.x;
    if (t < 32) {
        int sum = 0;
        for (int j = t; j < b; j += 32) sum += g_blksum[j];
#pragma unroll
        for (int off = 16; off; off >>= 1)
            sum += __shfl_xor_sync(0xffffffffu, sum, off);
        if (t == 0) s_off = sum;
    }
    __syncthreads();
    int i = b * 1024 + t;
    if (i < N) {
        int r = g_rowptr[i] + s_off;
        g_rowptr[i] = r;
        g_cursor[i] = r;
    }
}

__global__ void scatter_kernel(const int* __restrict__ ei, int E) {
    int i = (blockIdx.x * blockDim.x + threadIdx.x) * 4;
    if (i + 4 <= E) {
        int s0 = __ldg(ei + i),     s1 = __ldg(ei + i + 1);
        int s2 = __ldg(ei + i + 2), s3 = __ldg(ei + i + 3);
        int d0 = __ldg(ei + E + i),     d1 = __ldg(ei + E + i + 1);
        int d2 = __ldg(ei + E + i + 2), d3 = __ldg(ei + E + i + 3);
        int p0 = atomicAdd(&g_cursor[d0], 1);
        int p1 = atomicAdd(&g_cursor[d1], 1);
        int p2 = atomicAdd(&g_cursor[d2], 1);
        int p3 = atomicAdd(&g_cursor[d3], 1);
        g_csr_src[p0] = s0;
        g_csr_src[p1] = s1;
        g_csr_src[p2] = s2;
        g_csr_src[p3] = s3;
    } else {
        for (; i < E; ++i) {
            int s = __ldg(ei + i);
            int d = __ldg(ei + E + i);
            int pos = atomicAdd(&g_cursor[d], 1);
            g_csr_src[pos] = s;
        }
    }
}

// ---------------- fp16 HMMA GEMM (m16n8k16 + ldmatrix) + fused alphas -------
template <typename T>
__global__ void __launch_bounds__(256, 2)
gemm_fp16_kernel(const T* __restrict__ X, const float* __restrict__ Wm,
                 const float* __restrict__ a_s, const float* __restrict__ a_d,
                 int N) {
    extern __shared__ __half sm[];
    __half* Xs = sm;                   // [128][HPAD]
    __half* Ws = sm + 128 * HPAD;      // [128][HPAD]  (W[k][n], row-major k)
    const int tid = threadIdx.x;
    const int row0 = blockIdx.x * 128;

#pragma unroll
    for (int it = 0; it < 16; ++it) {
        int idx = it * 256 + tid;        // 0..4095
        int r = idx >> 5;                // row (X) / k (W), 0..127
        int q = idx & 31;                // 4-elem slot
        int gr = row0 + r;
        uint2 xpack = make_uint2(0u, 0u);
        if (gr < N) {
            if constexpr (sizeof(T) == 4) {
                float4 v = __ldcs((const float4*)&X[(size_t)gr * F + q * 4]);
                __half2 p0 = __floats2half2_rn(v.x, v.y);
                __half2 p1 = __floats2half2_rn(v.z, v.w);
                xpack.x = *reinterpret_cast<uint32_t*>(&p0);
                xpack.y = *reinterpret_cast<uint32_t*>(&p1);
            } else {
                xpack = __ldcs((const uint2*)&X[(size_t)gr * F + q * 4]);
            }
        }
        *(uint2*)&Xs[r * HPAD + q * 4] = xpack;

        float4 wv = *(const float4*)&Wm[(size_t)idx * 4];  // = W[r][q*4..+3]
        __half2 w0 = __floats2half2_rn(wv.x, wv.y);
        __half2 w1 = __floats2half2_rn(wv.z, wv.w);
        uint2 wpack;
        wpack.x = *reinterpret_cast<uint32_t*>(&w0);
        wpack.y = *reinterpret_cast<uint32_t*>(&w1);
        *(uint2*)&Ws[r * HPAD + q * 4] = wpack;
    }
    __syncthreads();

    const int w = tid >> 5, lane = tid & 31;
    const int g = lane >> 2, q = lane & 3;
    const int mrow = (w >> 1) * 32;
    const int cb = (w & 1) * 64;
    const int sel = lane >> 3, li = lane & 7;

    float acc[2][8][4];
#pragma unroll
    for (int mt = 0; mt < 2; ++mt)
#pragma unroll
        for (int j = 0; j < 8; ++j)
#pragma unroll
            for (int t = 0; t < 4; ++t) acc[mt][j][t] = 0.f;

    uint32_t xu = (uint32_t)__cvta_generic_to_shared(Xs);
    uint32_t wu = (uint32_t)__cvta_generic_to_shared(Ws);

    uint32_t aaddr[2], baddr[4];
#pragma unroll
    for (int mt = 0; mt < 2; ++mt)
        aaddr[mt] = xu + (uint32_t)(((mrow + mt * 16 + (sel & 1) * 8 + li) * HPAD
                                     + (sel >> 1) * 8) * 2);
#pragma unroll
    for (int p = 0; p < 4; ++p)
        baddr[p] = wu + (uint32_t)((((sel & 1) * 8 + li) * HPAD
                                    + cb + p * 16 + (sel >> 1) * 8) * 2);

#pragma unroll
    for (int ks = 0; ks < 8; ++ks) {
        uint32_t a[2][4];
#pragma unroll
        for (int mt = 0; mt < 2; ++mt) {
            asm volatile(
                "ldmatrix.sync.aligned.m8n8.x4.shared.b16 {%0,%1,%2,%3}, [%4];"
                : "=r"(a[mt][0]), "=r"(a[mt][1]), "=r"(a[mt][2]), "=r"(a[mt][3])
                : "r"(aaddr[mt]));
            aaddr[mt] += 32;                 // +16 halves along k
        }
        uint32_t b[4][4];
#pragma unroll
        for (int p = 0; p < 4; ++p) {
            asm volatile(
                "ldmatrix.sync.aligned.m8n8.x4.trans.shared.b16 {%0,%1,%2,%3}, [%4];"
                : "=r"(b[p][0]), "=r"(b[p][1]), "=r"(b[p][2]), "=r"(b[p][3])
                : "r"(baddr[p]));
            baddr[p] += 16 * HPAD * 2;       // +16 k rows
        }
#pragma unroll
        for (int j = 0; j < 8; ++j) {
            uint32_t b0 = b[j >> 1][(j & 1) * 2];
            uint32_t b1 = b[j >> 1][(j & 1) * 2 + 1];
#pragma unroll
            for (int mt = 0; mt < 2; ++mt) {
                asm volatile(
                    "mma.sync.aligned.m16n8k16.row.col.f32.f16.f16.f32 "
                    "{%0,%1,%2,%3}, {%4,%5,%6,%7}, {%8,%9}, {%0,%1,%2,%3};"
                    : "+f"(acc[mt][j][0]), "+f"(acc[mt][j][1]),
                      "+f"(acc[mt][j][2]), "+f"(acc[mt][j][3])
                    : "r"(a[mt][0]), "r"(a[mt][1]), "r"(a[mt][2]), "r"(a[mt][3]),
                      "r"(b0), "r"(b1));
            }
        }
    }

    // ---- epilogue: store h as fp16 + fused alpha partials (fp32 acc) -------
    float pa[4][2] = {{0.f, 0.f}, {0.f, 0.f}, {0.f, 0.f}, {0.f, 0.f}};
    float pd[4][2] = {{0.f, 0.f}, {0.f, 0.f}, {0.f, 0.f}, {0.f, 0.f}};
#pragma unroll
    for (int mt = 0; mt < 2; ++mt) {
#pragma unroll
        for (int j = 0; j < 8; ++j) {
            int col = cb + j * 8 + q * 2;
            float as0 = __ldg(&a_s[col]), as1 = __ldg(&a_s[col + 1]);
            float ad0 = __ldg(&a_d[col]), ad1 = __ldg(&a_d[col + 1]);
            int hh = j >> 2;
            float2 lo = make_float2(acc[mt][j][0], acc[mt][j][1]);  // row g
            float2 hi = make_float2(acc[mt][j][2], acc[mt][j][3]);  // row g+8
            pa[mt * 2 + 0][hh] += lo.x * as0 + lo.y * as1;
            pd[mt * 2 + 0][hh] += lo.x * ad0 + lo.y * ad1;
            pa[mt * 2 + 1][hh] += hi.x * as0 + hi.y * as1;
            pd[mt * 2 + 1][hh] += hi.x * ad0 + hi.y * ad1;
            int r_lo = row0 + mrow + mt * 16 + g;
            if (r_lo < N)
                *(__half2*)&g_h[(size_t)r_lo * F + col] = __floats2half2_rn(lo.x, lo.y);
            if (r_lo + 8 < N)
                *(__half2*)&g_h[(size_t)(r_lo + 8) * F + col] = __floats2half2_rn(hi.x, hi.y);
        }
    }
#pragma unroll
    for (int off = 1; off <= 2; off <<= 1) {
#pragma unroll
        for (int s = 0; s < 4; ++s)
#pragma unroll
            for (int hh = 0; hh < 2; ++hh) {
                pa[s][hh] += __shfl_xor_sync(0xffffffffu, pa[s][hh], off);
                pd[s][hh] += __shfl_xor_sync(0xffffffffu, pd[s][hh], off);
            }
    }
    if (q == 0) {
        int head_base = (w & 1) * 2;
#pragma unroll
        for (int s = 0; s < 4; ++s) {
            int mt = s >> 1, rh = s & 1;
            int row = row0 + mrow + mt * 16 + rh * 8 + g;
            if (row < N) {
#pragma unroll
                for (int hh = 0; hh < 2; ++hh) {
                    g_as[row * HEADS + head_base + hh] = pa[s][hh];
                    g_ad[row * HEADS + head_base + hh] = pd[s][hh];
                }
            }
        }
    }
}

// ---------------- CSR aggregation: warp/node, 2 edges per half-warp step ----
// lane = half*16 + sub. Each sub-lane covers 8 fp16 columns (16B = LDG.128).
// half 0 processes even pair slots, half 1 odd. One shfl_xor(16) merge at end.
template <int LAYER>
__global__ void __launch_bounds__(64)
aggregate_kernel(const float* __restrict__ bias,
                 float* __restrict__ out, int N, int write_splits) {
    int n = (blockIdx.x * blockDim.x + threadIdx.x) >> 5;
    int lane = threadIdx.x & 31;
    if (n >= N) return;
    int half = lane >> 4;      // 0/1
    int sub = lane & 15;       // 0..15
    int head = sub >> 2;       // 4 sub-lanes per head (8 cols each)
    int c = sub * 8;           // column base

    float adh = __ldg(&g_ad[n * HEADS + head]);
    float acc[8];
#pragma unroll
    for (int k = 0; k < 8; ++k) acc[k] = 0.f;
    float den = 0.f;

    int e = __ldg(&g_rowptr[n]);
    int end = e + __ldg(&g_deg[n]);

    // 4 edges per iteration: 2 pair-steps, each covering 2 edges (1 per half)
    for (; e + 4 <= end; e += 4) {
        int sa = __ldg(&g_csr_src[e + half]);
        int sb = __ldg(&g_csr_src[e + 2 + half]);
        float asa = __ldg(&g_as[sa * HEADS + head]);
        float asb = __ldg(&g_as[sb * HEADS + head]);
        uint4 ha = __ldg((const uint4*)&g_h[(size_t)sa * F + c]);
        uint4 hb = __ldg((const uint4*)&g_h[(size_t)sb * F + c]);
        float wa = leaky_exp(asa + adh);
        float wb = leaky_exp(asb + adh);
        den += wa + wb;
        const __half2* pa = (const __half2*)&ha;
        const __half2* pb = (const __half2*)&hb;
#pragma unroll
        for (int k = 0; k < 4; ++k) {
            float2 fa = __half22float2(pa[k]);
            float2 fb = __half22float2(pb[k]);
            acc[2 * k]     = fmaf(wa, fa.x, fmaf(wb, fb.x, acc[2 * k]));
            acc[2 * k + 1] = fmaf(wa, fa.y, fmaf(wb, fb.y, acc[2 * k + 1]));
        }
    }
    // remaining pair (2 edges)
    if (e + 2 <= end) {
        int s = __ldg(&g_csr_src[e + half]);
        float as = __ldg(&g_as[s * HEADS + head]);
        uint4 h = __ldg((const uint4*)&g_h[(size_t)s * F + c]);
        float w = leaky_exp(as + adh);
        den += w;
        const __half2* ph = (const __half2*)&h;
#pragma unroll
        for (int k = 0; k < 4; ++k) {
            float2 f = __half22float2(ph[k]);
            acc[2 * k]     = fmaf(w, f.x, acc[2 * k]);
            acc[2 * k + 1] = fmaf(w, f.y, acc[2 * k + 1]);
        }
        e += 2;
    }
    // odd leftover edge: half 0 only
    if (e < end && half == 0) {
        int s = __ldg(&g_csr_src[e]);
        float as = __ldg(&g_as[s * HEADS + head]);
        uint4 h = __ldg((const uint4*)&g_h[(size_t)s * F + c]);
        float w = leaky_exp(as + adh);
        den += w;
        const __half2* ph = (const __half2*)&h;
#pragma unroll
        for (int k = 0; k < 4; ++k) {
            float2 f = __half22float2(ph[k]);
            acc[2 * k]     = fmaf(w, f.x, acc[2 * k]);
            acc[2 * k + 1] = fmaf(w, f.y, acc[2 * k + 1]);
        }
    }

    // merge halves (lane l <-> l+16 cover identical columns)
    den += __shfl_xor_sync(0xffffffffu, den, 16);
#pragma unroll
    for (int k = 0; k < 8; ++k)
        acc[k] += __shfl_xor_sync(0xffffffffu, acc[k], 16);

    // self-loop (added once, after merge; both halves compute identically)
    float ws = leaky_exp(__ldg(&g_as[n * HEADS + head]) + adh);
    uint4 hv = __ldg((const uint4*)&g_h[(size_t)n * F + c]);
    den += ws;
    {
        const __half2* ph = (const __half2*)&hv;
#pragma unroll
        for (int k = 0; k < 4; ++k) {
            float2 f = __half22float2(ph[k]);
            acc[2 * k]     = fmaf(ws, f.x, acc[2 * k]);
            acc[2 * k + 1] = fmaf(ws, f.y, acc[2 * k + 1]);
        }
    }

    float inv = 1.f / (den + 1e-16f);
    float4 b0 = __ldg((const float4*)&bias[c]);
    float4 b1 = __ldg((const float4*)&bias[c + 4]);
    float v[8];
    v[0] = acc[0] * inv + b0.x; v[1] = acc[1] * inv + b0.y;
    v[2] = acc[2] * inv + b0.z; v[3] = acc[3] * inv + b0.w;
    v[4] = acc[4] * inv + b1.x; v[5] = acc[5] * inv + b1.y;
    v[6] = acc[6] * inv + b1.z; v[7] = acc[7] * inv + b1.w;

    if (half != 0) return;   // stores from half 0 (16 lanes cover full row)

    if (LAYER == 1) {
#pragma unroll
        for (int k = 0; k < 8; ++k)
            v[k] = v[k] > 0.f ? v[k] : expm1f(v[k]);
        uint4 packed;
        __half2 q0 = __floats2half2_rn(v[0], v[1]);
        __half2 q1 = __floats2half2_rn(v[2], v[3]);
        __half2 q2 = __floats2half2_rn(v[4], v[5]);
        __half2 q3 = __floats2half2_rn(v[6], v[7]);
        packed.x = *reinterpret_cast<uint32_t*>(&q0);
        packed.y = *reinterpret_cast<uint32_t*>(&q1);
        packed.z = *reinterpret_cast<uint32_t*>(&q2);
        packed.w = *reinterpret_cast<uint32_t*>(&q3);
        stcs4u((uint4*)&g_x2[(size_t)n * F + c], packed);
    } else {
        stcs4(&out[(size_t)n * F + c],     make_float4(v[0], v[1], v[2], v[3]));
        stcs4(&out[(size_t)n * F + c + 4], make_float4(v[4], v[5], v[6], v[7]));
        if (write_splits) {
            int off = (sub & 3) * 8;   // position within head (0..31)
            float* sp = &out[(size_t)N * F + (size_t)head * N * 32 + (size_t)n * 32 + off];
            stcs4(sp,     make_float4(v[0], v[1], v[2], v[3]));
            stcs4(sp + 4, make_float4(v[4], v[5], v[6], v[7]));
        }
    }
}

// ---------------- launch ----------------------------------------------------
// Side stream + events (lazily created on the uncaptured correctness call;
// captured work is identical on every call; no device memory allocated).
static cudaStream_t g_s2 = nullptr;
static cudaEvent_t g_ev_fork = nullptr, g_ev_join = nullptr;

extern "C" void kernel_launch(void* const* d_in, const int* in_sizes, int n_in,
                              void* d_out, int out_size) {
    const float* x   = (const float*)d_in[0];
    const int*   ei  = (const int*)d_in[1];
    const float* W1  = (const float*)d_in[2];
    const float* as1 = (const float*)d_in[3];
    const float* ad1 = (const float*)d_in[4];
    const float* b1  = (const float*)d_in[5];
    const float* W2  = (const float*)d_in[6];
    const float* as2 = (const float*)d_in[7];
    const float* ad2 = (const float*)d_in[8];
    const float* b2  = (const float*)d_in[9];

    int N = in_sizes[0] / F;
    int E = in_sizes[1] / 2;
    float* out = (float*)d_out;
    int write_splits = (out_size >= N * F * 2) ? 1 : 0;

    if (!g_s2) {
        cudaStreamCreateWithFlags(&g_s2, cudaStreamNonBlocking);
        cudaEventCreateWithFlags(&g_ev_fork, cudaEventDisableTiming);
        cudaEventCreateWithFlags(&g_ev_join, cudaEventDisableTiming);
    }

    __half* p_x2 = nullptr;
    cudaGetSymbolAddress((void**)&p_x2, g_x2);
    int* p_deg = nullptr;
    cudaGetSymbolAddress((void**)&p_deg, g_deg);

    const int SMEM_BYTES = 2 * 128 * HPAD * 2;   // Xs + Ws, fp16
    cudaFuncSetAttribute(gemm_fp16_kernel<float>,
                         cudaFuncAttributeMaxDynamicSharedMemorySize, SMEM_BYTES);
    cudaFuncSetAttribute(gemm_fp16_kernel<__half>,
                         cudaFuncAttributeMaxDynamicSharedMemorySize, SMEM_BYTES);

    int gb = (N + 127) / 128;
    int wb64 = (N * 32 + 63) / 64;       // 64-thread aggregate blocks
    int nb1024 = (N + 1023) / 1024;
    int eb4 = (E / 4 + 1 + 255) / 256;   // 4 edges/thread kernels

    // fork: gemm1 on side stream, CSR build on default stream
    cudaEventRecord(g_ev_fork, 0);
    cudaStreamWaitEvent(g_s2, g_ev_fork, 0);

    cudaMemsetAsync(p_deg, 0, (size_t)N * sizeof(int), 0);
    deg_kernel<<<eb4, 256>>>(ei, E);
    scan1_kernel<<<nb1024, 1024>>>(N);
    scan3_kernel<<<nb1024, 1024>>>(N);
    scatter_kernel<<<eb4, 256>>>(ei, E);                 // #4 (profiled)

    gemm_fp16_kernel<float><<<gb, 256, SMEM_BYTES, g_s2>>>(x, W1, as1, ad1, N);
    cudaEventRecord(g_ev_join, g_s2);
    cudaStreamWaitEvent(0, g_ev_join, 0);   // agg1 needs CSR + gemm1

    // ---- layer 1 aggregate, layer 2 ----
    aggregate_kernel<1><<<wb64, 64>>>(b1, out, N, 0);
    gemm_fp16_kernel<__half><<<gb, 256, SMEM_BYTES>>>(p_x2, W2, as2, ad2, N);
    aggregate_kernel<2><<<wb64, 64>>>(b2, out, N, write_splits);
}